// round 16
// baseline (speedup 1.0000x reference)
#include <cuda_runtime.h>
#include <cuda_fp16.h>
#include <math.h>
#include <stdint.h>

#define F_IN  512
#define F_HID 128
#define F_OUT 16
#define MAXN  100000
#define MAXE  1600000
#define MAXE2 (MAXE + 8 * MAXN)   // padded CSR capacity
#define SCAN_B 512
#define NSB   148

// ---- scratch (static device globals; no allocation allowed) ----
// zeroed-per-call block: [deg (float) | cnt | fill | cursor]
__device__ __align__(16) int g_zblk[3 * MAXN + 4];
#define G_DEG  ((float*)g_zblk)
#define G_CNT  (g_zblk + MAXN)
#define G_FILL (g_zblk + 2 * MAXN)
#define G_CUR  (g_zblk + 3 * MAXN)

__device__ float g_dinv [MAXN];
__device__ int   g_off  [MAXN];
__device__ __align__(16) int2 g_edge[MAXE2];      // CSR: (src, norm-as-int), padded
__device__ __align__(16) __half g_h1[(size_t)MAXN * F_HID];   // x @ W1 (fp16)
__device__ __align__(16) __half g_h2[(size_t)MAXN * F_HID];   // relu(agg) (fp16)
__device__ float g_z    [(size_t)MAXN * F_OUT];   // h2 @ W2
__device__ __align__(16) __half g_wt[F_HID * F_IN];   // W1^T fp16 [n][k]

// ======================= helpers ========================
__device__ __forceinline__ uint32_t smem_u32(const void* p) {
    uint32_t a;
    asm("{ .reg .u64 t; cvta.to.shared.u64 t, %1; cvt.u32.u64 %0, t; }"
        : "=r"(a) : "l"(p));
    return a;
}
#define SWZ64(o) ((o) ^ (((o) >> 3) & 0x30))

__device__ __forceinline__ void ldsm_x4(uint32_t* r, uint32_t addr) {
    asm volatile("ldmatrix.sync.aligned.m8n8.x4.shared.b16 {%0,%1,%2,%3}, [%4];"
                 : "=r"(r[0]), "=r"(r[1]), "=r"(r[2]), "=r"(r[3]) : "r"(addr));
}
__device__ __forceinline__ void mma_f16(float* d, const uint32_t* a, const uint32_t* b) {
    asm volatile(
        "mma.sync.aligned.m16n8k16.row.col.f32.f16.f16.f32 "
        "{%0,%1,%2,%3}, {%4,%5,%6,%7}, {%8,%9}, {%0,%1,%2,%3};"
        : "+f"(d[0]), "+f"(d[1]), "+f"(d[2]), "+f"(d[3])
        : "r"(a[0]), "r"(a[1]), "r"(a[2]), "r"(a[3]), "r"(b[0]), "r"(b[1]));
}
__device__ __forceinline__ void cp_async16(uint32_t dst, const void* src) {
    asm volatile("cp.async.ca.shared.global [%0], [%1], 16;" :: "r"(dst), "l"(src));
}
#define CP_COMMIT() asm volatile("cp.async.commit_group;" ::: "memory")
#define CP_WAIT0()  asm volatile("cp.async.wait_group 0;" ::: "memory")

// ======================= kernel 1: degree + count ============================
__global__ void deg_cnt_k(const int* __restrict__ dst, const float* __restrict__ ew, int E) {
    int e = blockIdx.x * blockDim.x + threadIdx.x;
    if (e < E) {
        int d = dst[e];
        atomicAdd(&G_DEG[d], ew[e]);
        atomicAdd(&G_CNT[d], 1);
    }
}

// ======================= kernel 2: scan+dinv+pad  ||  wconv ==================
__global__ __launch_bounds__(SCAN_B) void scanwconv_k(const float* __restrict__ W1,
                                                      int Nn, int nb) {
    if ((int)blockIdx.x >= nb) {
        int i = (blockIdx.x - nb) * SCAN_B + threadIdx.x;
        for (; i < F_HID * F_IN; i += 64 * SCAN_B) {
            int n = i >> 9;
            int k = i & 511;
            g_wt[i] = __float2half_rn(W1[(size_t)k * F_HID + n]);
        }
        return;
    }
    __shared__ int s[SCAN_B];
    __shared__ int sbase;
    int i = blockIdx.x * SCAN_B + threadIdx.x;
    int c  = (i < Nn) ? G_CNT[i] : 0;
    int cp = (c + 7) & ~7;                  // pad group to multiple of 8
    s[threadIdx.x] = cp;
    if (i < Nn) {
        float d = G_DEG[i] + 1.0f;          // self loop weight 1
        g_dinv[i] = d > 0.f ? rsqrtf(d) : 0.f;
    }
    __syncthreads();
#pragma unroll
    for (int o = 1; o < SCAN_B; o <<= 1) {
        int t = (threadIdx.x >= o) ? s[threadIdx.x - o] : 0;
        __syncthreads();
        s[threadIdx.x] += t;
        __syncthreads();
    }
    if (threadIdx.x == SCAN_B - 1)
        sbase = atomicAdd(G_CUR, s[SCAN_B - 1]);
    __syncthreads();
    if (i < Nn) {
        int base = sbase + s[threadIdx.x] - cp;
        g_off[i] = base;
        G_CNT[i] = cp;
        for (int k = c; k < cp; k++)
            g_edge[base + k] = make_int2(0, 0);
    }
}

// ======================= kernel 3: scatter || GEMM1 ==========================
#define KC 32
#define STG 16384
#define PL_A 0
#define PL_B 8192
#define GEMM_SMEM (2 * STG)

__global__ __launch_bounds__(256, 2) void gemmscat_k(const float* __restrict__ x,
                                                     const int* __restrict__ src,
                                                     const int* __restrict__ dst,
                                                     const float* __restrict__ ew,
                                                     int Nn, int E) {
    if (blockIdx.x < NSB) {
        int t = blockIdx.x * 256 + threadIdx.x;
        const int STRD = NSB * 256;
        for (int e = t; e < E; e += STRD) {
            int s = src[e];
            int d = dst[e];
            int pos = g_off[d] + atomicAdd(&G_FILL[d], 1);
            float norm = g_dinv[s] * ew[e] * g_dinv[d];
            g_edge[pos] = make_int2(s, __float_as_int(norm));
        }
        return;
    }

    extern __shared__ char smem[];
    uint32_t sb = smem_u32(smem);
    int tid  = threadIdx.x;
    int lane = tid & 31;
    int wid  = tid >> 5;
    int wm   = wid & 3;
    int wn   = wid >> 2;
    int row0 = (blockIdx.x - NSB) * 128;

#pragma unroll
    for (int i = 0; i < 2; i++) {
        int u = i * 256 + tid;
        int n = u >> 2;
        int c = u & 3;
        uint32_t off = SWZ64((uint32_t)(n * 64 + c * 16));
        cp_async16(sb + PL_B + off, g_wt + (size_t)n * F_IN + c * 8);
    }
    CP_COMMIT();

    float4 pA[4];
#pragma unroll
    for (int i = 0; i < 4; i++) {
        int u = i * 256 + tid;
        int r = u >> 3;
        int c4 = (u & 7) * 4;
        int gr = row0 + r;
        pA[i] = make_float4(0.f, 0.f, 0.f, 0.f);
        if (gr < Nn) pA[i] = *(const float4*)(x + (size_t)gr * F_IN + c4);
    }

    float acc[2][8][4];
#pragma unroll
    for (int a = 0; a < 2; a++)
#pragma unroll
        for (int b = 0; b < 8; b++)
#pragma unroll
            for (int c = 0; c < 4; c++) acc[a][b][c] = 0.f;

    for (int it = 0; it < F_IN / KC; it++) {
        int s = it & 1;
        char*    sm_s = smem + s * STG;
        uint32_t sb_s = sb + s * STG;

#pragma unroll
        for (int i = 0; i < 4; i++) {
            int u = i * 256 + tid;
            int r = u >> 3;
            int c4 = (u & 7) * 4;
            __half2 p0 = __floats2half2_rn(pA[i].x, pA[i].y);
            __half2 p1 = __floats2half2_rn(pA[i].z, pA[i].w);
            uint32_t off = SWZ64((uint32_t)(r * 64 + c4 * 2));
            *(uint2*)(sm_s + PL_A + off) =
                make_uint2(*(uint32_t*)&p0, *(uint32_t*)&p1);
        }
        CP_WAIT0();
        __syncthreads();

        if (it + 1 < F_IN / KC) {
            int kn = (it + 1) * KC;
            uint32_t sb_n = sb + (s ^ 1) * STG;
#pragma unroll
            for (int i = 0; i < 2; i++) {
                int u = i * 256 + tid;
                int n = u >> 2;
                int c = u & 3;
                uint32_t off = SWZ64((uint32_t)(n * 64 + c * 16));
                cp_async16(sb_n + PL_B + off, g_wt + (size_t)n * F_IN + kn + c * 8);
            }
            CP_COMMIT();
#pragma unroll
            for (int i = 0; i < 4; i++) {
                int u = i * 256 + tid;
                int r = u >> 3;
                int c4 = (u & 7) * 4;
                int gr = row0 + r;
                pA[i] = make_float4(0.f, 0.f, 0.f, 0.f);
                if (gr < Nn) pA[i] = *(const float4*)(x + (size_t)gr * F_IN + kn + c4);
            }
        }

#pragma unroll
        for (int ks = 0; ks < 2; ks++) {
            uint32_t a[2][4];
#pragma unroll
            for (int mt = 0; mt < 2; mt++) {
                uint32_t off = SWZ64((uint32_t)((wm * 32 + mt * 16 + (lane & 15)) * 64
                                                + ks * 32 + (lane >> 4) * 16));
                ldsm_x4(a[mt], sb_s + PL_A + off);
            }
#pragma unroll
            for (int ntp = 0; ntp < 4; ntp++) {
                uint32_t offB = SWZ64((uint32_t)((wn * 64 + ntp * 16 + (lane & 7)
                                                  + ((lane >> 4) & 1) * 8) * 64
                                                 + ks * 32 + ((lane >> 3) & 1) * 16));
                uint32_t b[4];
                ldsm_x4(b, sb_s + PL_B + offB);
#pragma unroll
                for (int sub = 0; sub < 2; sub++) {
#pragma unroll
                    for (int mt = 0; mt < 2; mt++)
                        mma_f16(acc[mt][ntp * 2 + sub], a[mt], b + sub * 2);
                }
            }
        }
    }

    int g4 = lane >> 2;
    int tg = lane & 3;
#pragma unroll
    for (int mt = 0; mt < 2; mt++) {
        int rbase = row0 + wm * 32 + mt * 16 + g4;
#pragma unroll
        for (int nt = 0; nt < 8; nt++) {
            int c = wn * 64 + nt * 8 + tg * 2;
            float* d = acc[mt][nt];
            if (rbase < Nn)
                *(__half2*)(g_h1 + (size_t)rbase * F_HID + c) = __floats2half2_rn(d[0], d[1]);
            if (rbase + 8 < Nn)
                *(__half2*)(g_h1 + (size_t)(rbase + 8) * F_HID + c) = __floats2half2_rn(d[2], d[3]);
        }
    }
}

// ======================= kernel 4: layer-1 gather ============================
// 2 edges/lane-half (contiguous 4-edge runs per half, int4 edge loads), uint4
// rows, padded groups + self loop + bias + relu -> g_h2 (fp16). No epilogue.
__global__ __launch_bounds__(256, 4) void agg1_gather_k(const float* __restrict__ b1,
                                                        int Nn) {
    int tid   = threadIdx.x;
    int lane  = tid & 31;
    int l16   = lane & 15;
    int half  = lane >> 4;
    int warp  = (blockIdx.x * blockDim.x + tid) >> 5;
    int nwarp = (gridDim.x * blockDim.x) >> 5;

    float bb[8];
    *(float4*)&bb[0] = *(const float4*)(b1 + l16 * 8);
    *(float4*)&bb[4] = *(const float4*)(b1 + l16 * 8 + 4);

    int node = warp;
    int base = 0, cnt = 0;
    if (node < Nn) { base = g_off[node]; cnt = G_CNT[node]; }   // cnt %8 == 0

    while (node < Nn) {
        int nnode = node + nwarp;
        int nbase = 0, ncnt = 0;
        if (nnode < Nn) { nbase = __ldg(g_off + nnode); ncnt = __ldg(G_CNT + nnode); }

        float a[8];
#pragma unroll
        for (int j = 0; j < 8; j++) a[j] = 0.f;

        for (int i = 0; i < cnt; i += 8) {
            // this half handles edges i+4*half .. i+4*half+3 (2x int4 loads)
            const int4* ep = (const int4*)(g_edge + base + i + 4 * half);
            int4 e01 = __ldg(ep);
            int4 e23 = __ldg(ep + 1);
            uint4 v0 = __ldg(((const uint4*)(g_h1 + (size_t)e01.x * F_HID)) + l16);
            uint4 v1 = __ldg(((const uint4*)(g_h1 + (size_t)e01.z * F_HID)) + l16);
            uint4 v2 = __ldg(((const uint4*)(g_h1 + (size_t)e23.x * F_HID)) + l16);
            uint4 v3 = __ldg(((const uint4*)(g_h1 + (size_t)e23.z * F_HID)) + l16);
#pragma unroll
            for (int t = 0; t < 4; t++) {
                uint4 v = (t == 0) ? v0 : (t == 1) ? v1 : (t == 2) ? v2 : v3;
                float nm = __int_as_float((t == 0) ? e01.y : (t == 1) ? e01.w
                                          : (t == 2) ? e23.y : e23.w);
                float2 f0 = __half22float2(*(__half2*)&v.x);
                float2 f1 = __half22float2(*(__half2*)&v.y);
                float2 f2 = __half22float2(*(__half2*)&v.z);
                float2 f3 = __half22float2(*(__half2*)&v.w);
                a[0] = fmaf(f0.x, nm, a[0]);
                a[1] = fmaf(f0.y, nm, a[1]);
                a[2] = fmaf(f1.x, nm, a[2]);
                a[3] = fmaf(f1.y, nm, a[3]);
                a[4] = fmaf(f2.x, nm, a[4]);
                a[5] = fmaf(f2.y, nm, a[5]);
                a[6] = fmaf(f3.x, nm, a[6]);
                a[7] = fmaf(f3.y, nm, a[7]);
            }
        }

        // merge halves: lane l and l+16 cover the same 8 cols
#pragma unroll
        for (int j = 0; j < 8; j++)
            a[j] += __shfl_xor_sync(0xffffffffu, a[j], 16);

        // self loop + bias + relu, write fp16 (half 0 lanes store)
        float dn  = g_dinv[node];
        float dn2 = dn * dn;
        uint4 sv = __ldg(((const uint4*)(g_h1 + (size_t)node * F_HID)) + l16);
        float2 s0 = __half22float2(*(__half2*)&sv.x);
        float2 s1 = __half22float2(*(__half2*)&sv.y);
        float2 s2 = __half22float2(*(__half2*)&sv.z);
        float2 s3 = __half22float2(*(__half2*)&sv.w);
        float h[8];
        h[0] = fmaxf(a[0] + s0.x * dn2 + bb[0], 0.f);
        h[1] = fmaxf(a[1] + s0.y * dn2 + bb[1], 0.f);
        h[2] = fmaxf(a[2] + s1.x * dn2 + bb[2], 0.f);
        h[3] = fmaxf(a[3] + s1.y * dn2 + bb[3], 0.f);
        h[4] = fmaxf(a[4] + s2.x * dn2 + bb[4], 0.f);
        h[5] = fmaxf(a[5] + s2.y * dn2 + bb[5], 0.f);
        h[6] = fmaxf(a[6] + s3.x * dn2 + bb[6], 0.f);
        h[7] = fmaxf(a[7] + s3.y * dn2 + bb[7], 0.f);

        if (half == 0) {
            __half2 o0 = __floats2half2_rn(h[0], h[1]);
            __half2 o1 = __floats2half2_rn(h[2], h[3]);
            __half2 o2 = __floats2half2_rn(h[4], h[5]);
            __half2 o3 = __floats2half2_rn(h[6], h[7]);
            ((uint4*)(g_h2 + (size_t)node * F_HID))[l16] =
                make_uint4(*(uint32_t*)&o0, *(uint32_t*)&o1,
                           *(uint32_t*)&o2, *(uint32_t*)&o3);
        }

        node = nnode;
        base = nbase;
        cnt  = ncnt;
    }
}

// ======================= kernel 5: GEMM2 =====================================
// g_z = h2 @ W2; warp per node, W2 in registers, butterfly reduction
__global__ __launch_bounds__(256, 2) void gemm2_k(const float* __restrict__ W2, int Nn) {
    int lane  = threadIdx.x & 31;
    int warp  = (blockIdx.x * blockDim.x + threadIdx.x) >> 5;
    int nwarp = (gridDim.x * blockDim.x) >> 5;

    float w[4][16];
#pragma unroll
    for (int j = 0; j < 4; j++)
#pragma unroll
        for (int o = 0; o < 16; o++)
            w[j][o] = __ldg(W2 + (size_t)(lane * 4 + j) * F_OUT + o);

    for (int node = warp; node < Nn; node += nwarp) {
        uint2 hv = __ldg(((const uint2*)(g_h2 + (size_t)node * F_HID)) + lane);
        float2 f0 = __half22float2(*(__half2*)&hv.x);
        float2 f1 = __half22float2(*(__half2*)&hv.y);

        float v16[16];
#pragma unroll
        for (int o = 0; o < 16; o++)
            v16[o] = f0.x * w[0][o] + f0.y * w[1][o] + f1.x * w[2][o] + f1.y * w[3][o];

        // butterfly split reduction: 16 shuffles
        {
            bool hi = (lane & 16) != 0;
#pragma unroll
            for (int j = 0; j < 8; j++) {
                float keep = hi ? v16[j + 8] : v16[j];
                float send = hi ? v16[j] : v16[j + 8];
                v16[j] = keep + __shfl_xor_sync(0xffffffffu, send, 16);
            }
        }
        {
            bool hi = (lane & 8) != 0;
#pragma unroll
            for (int j = 0; j < 4; j++) {
                float keep = hi ? v16[j + 4] : v16[j];
                float send = hi ? v16[j] : v16[j + 4];
                v16[j] = keep + __shfl_xor_sync(0xffffffffu, send, 8);
            }
        }
        {
            bool hi = (lane & 4) != 0;
#pragma unroll
            for (int j = 0; j < 2; j++) {
                float keep = hi ? v16[j + 2] : v16[j];
                float send = hi ? v16[j] : v16[j + 2];
                v16[j] = keep + __shfl_xor_sync(0xffffffffu, send, 4);
            }
        }
        {
            bool hi = (lane & 2) != 0;
            float keep = hi ? v16[1] : v16[0];
            float send = hi ? v16[0] : v16[1];
            v16[0] = keep + __shfl_xor_sync(0xffffffffu, send, 2);
        }
        v16[0] += __shfl_xor_sync(0xffffffffu, v16[0], 1);
        if (!(lane & 1))
            g_z[(size_t)node * F_OUT + (lane >> 1)] = v16[0];
    }
}

// ======================= kernel 6: fused layer-2 =============================
// padded groups, int4 edge loads, 16 lanes per node + log_softmax -> out
__global__ __launch_bounds__(256, 6) void agg2_fused_k(const float* __restrict__ b2,
                                                       float* __restrict__ out,
                                                       int Nn) {
    int lane16 = threadIdx.x & 15;
    int gid    = (blockIdx.x * blockDim.x + threadIdx.x) >> 4;
    int ngrp   = (gridDim.x * blockDim.x) >> 4;
    float bias = b2[lane16];

    int node = gid;
    int base = 0, cnt = 0;
    if (node < Nn) { base = g_off[node]; cnt = G_CNT[node]; }

    while (node < Nn) {
        int nnode = node + ngrp;
        int nbase = 0, ncnt = 0;
        if (nnode < Nn) { nbase = __ldg(g_off + nnode); ncnt = __ldg(G_CNT + nnode); }

        float acc[4] = {0.f, 0.f, 0.f, 0.f};
        for (int i = 0; i < cnt; i += 8) {
            const int4* ep = (const int4*)(g_edge + base + i);
            int4 p0 = __ldg(ep);
            int4 p1 = __ldg(ep + 1);
            int4 p2 = __ldg(ep + 2);
            int4 p3 = __ldg(ep + 3);
            float zv[8];
            zv[0] = __ldg(g_z + (size_t)p0.x * F_OUT + lane16);
            zv[1] = __ldg(g_z + (size_t)p0.z * F_OUT + lane16);
            zv[2] = __ldg(g_z + (size_t)p1.x * F_OUT + lane16);
            zv[3] = __ldg(g_z + (size_t)p1.z * F_OUT + lane16);
            zv[4] = __ldg(g_z + (size_t)p2.x * F_OUT + lane16);
            zv[5] = __ldg(g_z + (size_t)p2.z * F_OUT + lane16);
            zv[6] = __ldg(g_z + (size_t)p3.x * F_OUT + lane16);
            zv[7] = __ldg(g_z + (size_t)p3.z * F_OUT + lane16);
            acc[0] = fmaf(zv[0], __int_as_float(p0.y), acc[0]);
            acc[1] = fmaf(zv[1], __int_as_float(p0.w), acc[1]);
            acc[2] = fmaf(zv[2], __int_as_float(p1.y), acc[2]);
            acc[3] = fmaf(zv[3], __int_as_float(p1.w), acc[3]);
            acc[0] = fmaf(zv[4], __int_as_float(p2.y), acc[0]);
            acc[1] = fmaf(zv[5], __int_as_float(p2.w), acc[1]);
            acc[2] = fmaf(zv[6], __int_as_float(p3.y), acc[2]);
            acc[3] = fmaf(zv[7], __int_as_float(p3.w), acc[3]);
        }

        float dn  = g_dinv[node];
        float dn2 = dn * dn;
        float l = acc[0] + acc[1] + acc[2] + acc[3]
                + g_z[(size_t)node * F_OUT + lane16] * dn2 + bias;

        float m = l;
#pragma unroll
        for (int o = 8; o >= 1; o >>= 1)
            m = fmaxf(m, __shfl_xor_sync(0xffffffffu, m, o));
        float e = __expf(l - m);
        float sum = e;
#pragma unroll
        for (int o = 8; o >= 1; o >>= 1)
            sum += __shfl_xor_sync(0xffffffffu, sum, o);

        out[(size_t)node * F_OUT + lane16] = l - m - __logf(sum);

        node = nnode;
        base = nbase;
        cnt  = ncnt;
    }
}

// ---------------------------------------------------------------------------
extern "C" void kernel_launch(void* const* d_in, const int* in_sizes, int n_in,
                              void* d_out, int out_size) {
    const float* x  = (const float*)d_in[0];
    const int*   ei = (const int*)  d_in[1];
    const float* ew = (const float*)d_in[2];
    const float* W1 = (const float*)d_in[3];
    const float* b1 = (const float*)d_in[4];
    const float* W2 = (const float*)d_in[5];
    const float* b2 = (const float*)d_in[6];
    float* out = (float*)d_out;

    int Nn = in_sizes[0] / F_IN;
    int E  = in_sizes[1] / 2;
    const int* src = ei;
    const int* dst = ei + E;
    int nb = (Nn + SCAN_B - 1) / SCAN_B;

    static void* zptr = nullptr;
    static bool attr_set = false;
    if (!zptr) cudaGetSymbolAddress(&zptr, g_zblk);
    if (!attr_set) {
        cudaFuncSetAttribute(gemmscat_k, cudaFuncAttributeMaxDynamicSharedMemorySize,
                             GEMM_SMEM);
        attr_set = true;
    }

    cudaMemsetAsync(zptr, 0, (size_t)(3 * MAXN + 4) * sizeof(int), 0);
    deg_cnt_k<<<(E + 255) / 256, 256>>>(dst, ew, E);                       // k1
    scanwconv_k<<<nb + 64, SCAN_B>>>(W1, Nn, nb);                          // k2
    gemmscat_k<<<NSB + (Nn + 127) / 128, 256, GEMM_SMEM>>>(x, src, dst,
                                                           ew, Nn, E);    // k3
    agg1_gather_k<<<148 * 4, 256>>>(b1, Nn);                               // k4 <- profiled
    gemm2_k<<<148 * 2, 256>>>(W2, Nn);                                     // k5
    agg2_fused_k<<<148 * 6, 256>>>(b2, out, Nn);                           // k6
}

// round 17
// speedup vs baseline: 1.1621x; 1.1621x over previous
#include <cuda_runtime.h>
#include <cuda_fp16.h>
#include <math.h>
#include <stdint.h>

#define F_IN  512
#define F_HID 128
#define F_OUT 16
#define MAXN  100000
#define MAXE  1600000
#define MAXE2 (MAXE + 8 * MAXN)   // padded CSR capacity
#define SCAN_B 512
#define NSB   148

// ---- scratch (static device globals; no allocation allowed) ----
__device__ __align__(16) int g_zblk[3 * MAXN + 4];
#define G_DEG  ((float*)g_zblk)
#define G_CNT  (g_zblk + MAXN)
#define G_FILL (g_zblk + 2 * MAXN)
#define G_CUR  (g_zblk + 3 * MAXN)

__device__ float g_dinv [MAXN];
__device__ int   g_off  [MAXN];
__device__ __align__(16) int2 g_edge[MAXE2];      // CSR: (src, norm-as-int), padded
__device__ __align__(16) __half g_h1[(size_t)MAXN * F_HID];   // x @ W1 (fp16)
__device__ __align__(16) __half g_h2[(size_t)MAXN * F_HID];   // relu(agg) (fp16)
__device__ float g_z    [(size_t)MAXN * F_OUT];   // h2 @ W2
__device__ __align__(16) __half g_wt [F_HID * F_IN];   // W1^T fp16 [n][k]
__device__ __align__(16) __half g_wt2[F_OUT * F_HID];  // W2^T fp16 [o][k]

// ======================= helpers ========================
__device__ __forceinline__ uint32_t smem_u32(const void* p) {
    uint32_t a;
    asm("{ .reg .u64 t; cvta.to.shared.u64 t, %1; cvt.u32.u64 %0, t; }"
        : "=r"(a) : "l"(p));
    return a;
}
#define SWZ64(o) ((o) ^ (((o) >> 3) & 0x30))

__device__ __forceinline__ void ldsm_x4(uint32_t* r, uint32_t addr) {
    asm volatile("ldmatrix.sync.aligned.m8n8.x4.shared.b16 {%0,%1,%2,%3}, [%4];"
                 : "=r"(r[0]), "=r"(r[1]), "=r"(r[2]), "=r"(r[3]) : "r"(addr));
}
__device__ __forceinline__ void mma_f16(float* d, const uint32_t* a, const uint32_t* b) {
    asm volatile(
        "mma.sync.aligned.m16n8k16.row.col.f32.f16.f16.f32 "
        "{%0,%1,%2,%3}, {%4,%5,%6,%7}, {%8,%9}, {%0,%1,%2,%3};"
        : "+f"(d[0]), "+f"(d[1]), "+f"(d[2]), "+f"(d[3])
        : "r"(a[0]), "r"(a[1]), "r"(a[2]), "r"(a[3]), "r"(b[0]), "r"(b[1]));
}
__device__ __forceinline__ void cp_async16(uint32_t dst, const void* src) {
    asm volatile("cp.async.ca.shared.global [%0], [%1], 16;" :: "r"(dst), "l"(src));
}
#define CP_COMMIT() asm volatile("cp.async.commit_group;" ::: "memory")
#define CP_WAIT0()  asm volatile("cp.async.wait_group 0;" ::: "memory")

// ======================= kernel 1: degree + count ============================
__global__ void deg_cnt_k(const int* __restrict__ dst, const float* __restrict__ ew, int E) {
    int e = blockIdx.x * blockDim.x + threadIdx.x;
    if (e < E) {
        int d = dst[e];
        atomicAdd(&G_DEG[d], ew[e]);
        atomicAdd(&G_CNT[d], 1);
    }
}

// ======================= kernel 2: scan+dinv+pad || wconv(W1,W2) =============
__global__ __launch_bounds__(SCAN_B) void scanwconv_k(const float* __restrict__ W1,
                                                      const float* __restrict__ W2,
                                                      int Nn, int nb) {
    if ((int)blockIdx.x >= nb) {
        int i = (blockIdx.x - nb) * SCAN_B + threadIdx.x;
        // W2^T fp16 (2048 elems) handled by the first extra block's threads
        if (blockIdx.x == (unsigned)nb && threadIdx.x < 512) {
            for (int j = threadIdx.x; j < F_OUT * F_HID; j += 512) {
                int o = j >> 7;
                int k = j & 127;
                g_wt2[j] = __float2half_rn(W2[(size_t)k * F_OUT + o]);
            }
        }
        for (; i < F_HID * F_IN; i += 64 * SCAN_B) {
            int n = i >> 9;
            int k = i & 511;
            g_wt[i] = __float2half_rn(W1[(size_t)k * F_HID + n]);
        }
        return;
    }
    __shared__ int s[SCAN_B];
    __shared__ int sbase;
    int i = blockIdx.x * SCAN_B + threadIdx.x;
    int c  = (i < Nn) ? G_CNT[i] : 0;
    int cp = (c + 7) & ~7;
    s[threadIdx.x] = cp;
    if (i < Nn) {
        float d = G_DEG[i] + 1.0f;          // self loop weight 1
        g_dinv[i] = d > 0.f ? rsqrtf(d) : 0.f;
    }
    __syncthreads();
#pragma unroll
    for (int o = 1; o < SCAN_B; o <<= 1) {
        int t = (threadIdx.x >= o) ? s[threadIdx.x - o] : 0;
        __syncthreads();
        s[threadIdx.x] += t;
        __syncthreads();
    }
    if (threadIdx.x == SCAN_B - 1)
        sbase = atomicAdd(G_CUR, s[SCAN_B - 1]);
    __syncthreads();
    if (i < Nn) {
        int base = sbase + s[threadIdx.x] - cp;
        g_off[i] = base;
        G_CNT[i] = cp;
        for (int k = c; k < cp; k++)
            g_edge[base + k] = make_int2(0, 0);
    }
}

// ======================= kernel 3: scatter || GEMM1 ==========================
#define KC 32
#define STG 16384
#define PL_A 0
#define PL_B 8192
#define GEMM_SMEM (2 * STG)

__global__ __launch_bounds__(256, 2) void gemmscat_k(const float* __restrict__ x,
                                                     const int* __restrict__ src,
                                                     const int* __restrict__ dst,
                                                     const float* __restrict__ ew,
                                                     int Nn, int E) {
    if (blockIdx.x < NSB) {
        int t = blockIdx.x * 256 + threadIdx.x;
        const int STRD = NSB * 256;
        for (int e = t; e < E; e += STRD) {
            int s = src[e];
            int d = dst[e];
            int pos = g_off[d] + atomicAdd(&G_FILL[d], 1);
            float norm = g_dinv[s] * ew[e] * g_dinv[d];
            g_edge[pos] = make_int2(s, __float_as_int(norm));
        }
        return;
    }

    extern __shared__ char smem[];
    uint32_t sb = smem_u32(smem);
    int tid  = threadIdx.x;
    int lane = tid & 31;
    int wid  = tid >> 5;
    int wm   = wid & 3;
    int wn   = wid >> 2;
    int row0 = (blockIdx.x - NSB) * 128;

#pragma unroll
    for (int i = 0; i < 2; i++) {
        int u = i * 256 + tid;
        int n = u >> 2;
        int c = u & 3;
        uint32_t off = SWZ64((uint32_t)(n * 64 + c * 16));
        cp_async16(sb + PL_B + off, g_wt + (size_t)n * F_IN + c * 8);
    }
    CP_COMMIT();

    float4 pA[4];
#pragma unroll
    for (int i = 0; i < 4; i++) {
        int u = i * 256 + tid;
        int r = u >> 3;
        int c4 = (u & 7) * 4;
        int gr = row0 + r;
        pA[i] = make_float4(0.f, 0.f, 0.f, 0.f);
        if (gr < Nn) pA[i] = *(const float4*)(x + (size_t)gr * F_IN + c4);
    }

    float acc[2][8][4];
#pragma unroll
    for (int a = 0; a < 2; a++)
#pragma unroll
        for (int b = 0; b < 8; b++)
#pragma unroll
            for (int c = 0; c < 4; c++) acc[a][b][c] = 0.f;

    for (int it = 0; it < F_IN / KC; it++) {
        int s = it & 1;
        char*    sm_s = smem + s * STG;
        uint32_t sb_s = sb + s * STG;

#pragma unroll
        for (int i = 0; i < 4; i++) {
            int u = i * 256 + tid;
            int r = u >> 3;
            int c4 = (u & 7) * 4;
            __half2 p0 = __floats2half2_rn(pA[i].x, pA[i].y);
            __half2 p1 = __floats2half2_rn(pA[i].z, pA[i].w);
            uint32_t off = SWZ64((uint32_t)(r * 64 + c4 * 2));
            *(uint2*)(sm_s + PL_A + off) =
                make_uint2(*(uint32_t*)&p0, *(uint32_t*)&p1);
        }
        CP_WAIT0();
        __syncthreads();

        if (it + 1 < F_IN / KC) {
            int kn = (it + 1) * KC;
            uint32_t sb_n = sb + (s ^ 1) * STG;
#pragma unroll
            for (int i = 0; i < 2; i++) {
                int u = i * 256 + tid;
                int n = u >> 2;
                int c = u & 3;
                uint32_t off = SWZ64((uint32_t)(n * 64 + c * 16));
                cp_async16(sb_n + PL_B + off, g_wt + (size_t)n * F_IN + kn + c * 8);
            }
            CP_COMMIT();
#pragma unroll
            for (int i = 0; i < 4; i++) {
                int u = i * 256 + tid;
                int r = u >> 3;
                int c4 = (u & 7) * 4;
                int gr = row0 + r;
                pA[i] = make_float4(0.f, 0.f, 0.f, 0.f);
                if (gr < Nn) pA[i] = *(const float4*)(x + (size_t)gr * F_IN + kn + c4);
            }
        }

#pragma unroll
        for (int ks = 0; ks < 2; ks++) {
            uint32_t a[2][4];
#pragma unroll
            for (int mt = 0; mt < 2; mt++) {
                uint32_t off = SWZ64((uint32_t)((wm * 32 + mt * 16 + (lane & 15)) * 64
                                                + ks * 32 + (lane >> 4) * 16));
                ldsm_x4(a[mt], sb_s + PL_A + off);
            }
#pragma unroll
            for (int ntp = 0; ntp < 4; ntp++) {
                uint32_t offB = SWZ64((uint32_t)((wn * 64 + ntp * 16 + (lane & 7)
                                                  + ((lane >> 4) & 1) * 8) * 64
                                                 + ks * 32 + ((lane >> 3) & 1) * 16));
                uint32_t b[4];
                ldsm_x4(b, sb_s + PL_B + offB);
#pragma unroll
                for (int sub = 0; sub < 2; sub++) {
#pragma unroll
                    for (int mt = 0; mt < 2; mt++)
                        mma_f16(acc[mt][ntp * 2 + sub], a[mt], b + sub * 2);
                }
            }
        }
    }

    int g4 = lane >> 2;
    int tg = lane & 3;
#pragma unroll
    for (int mt = 0; mt < 2; mt++) {
        int rbase = row0 + wm * 32 + mt * 16 + g4;
#pragma unroll
        for (int nt = 0; nt < 8; nt++) {
            int c = wn * 64 + nt * 8 + tg * 2;
            float* d = acc[mt][nt];
            if (rbase < Nn)
                *(__half2*)(g_h1 + (size_t)rbase * F_HID + c) = __floats2half2_rn(d[0], d[1]);
            if (rbase + 8 < Nn)
                *(__half2*)(g_h1 + (size_t)(rbase + 8) * F_HID + c) = __floats2half2_rn(d[2], d[3]);
        }
    }
}

// ======================= kernel 4: layer-1 gather ============================
// [byte-identical to round 16 — 51.9us verified]
__global__ __launch_bounds__(256, 4) void agg1_gather_k(const float* __restrict__ b1,
                                                        int Nn) {
    int tid   = threadIdx.x;
    int lane  = tid & 31;
    int l16   = lane & 15;
    int half  = lane >> 4;
    int warp  = (blockIdx.x * blockDim.x + tid) >> 5;
    int nwarp = (gridDim.x * blockDim.x) >> 5;

    float bb[8];
    *(float4*)&bb[0] = *(const float4*)(b1 + l16 * 8);
    *(float4*)&bb[4] = *(const float4*)(b1 + l16 * 8 + 4);

    int node = warp;
    int base = 0, cnt = 0;
    if (node < Nn) { base = g_off[node]; cnt = G_CNT[node]; }

    while (node < Nn) {
        int nnode = node + nwarp;
        int nbase = 0, ncnt = 0;
        if (nnode < Nn) { nbase = __ldg(g_off + nnode); ncnt = __ldg(G_CNT + nnode); }

        float a[8];
#pragma unroll
        for (int j = 0; j < 8; j++) a[j] = 0.f;

        for (int i = 0; i < cnt; i += 8) {
            const int4* ep = (const int4*)(g_edge + base + i + 4 * half);
            int4 e01 = __ldg(ep);
            int4 e23 = __ldg(ep + 1);
            uint4 v0 = __ldg(((const uint4*)(g_h1 + (size_t)e01.x * F_HID)) + l16);
            uint4 v1 = __ldg(((const uint4*)(g_h1 + (size_t)e01.z * F_HID)) + l16);
            uint4 v2 = __ldg(((const uint4*)(g_h1 + (size_t)e23.x * F_HID)) + l16);
            uint4 v3 = __ldg(((const uint4*)(g_h1 + (size_t)e23.z * F_HID)) + l16);
#pragma unroll
            for (int t = 0; t < 4; t++) {
                uint4 v = (t == 0) ? v0 : (t == 1) ? v1 : (t == 2) ? v2 : v3;
                float nm = __int_as_float((t == 0) ? e01.y : (t == 1) ? e01.w
                                          : (t == 2) ? e23.y : e23.w);
                float2 f0 = __half22float2(*(__half2*)&v.x);
                float2 f1 = __half22float2(*(__half2*)&v.y);
                float2 f2 = __half22float2(*(__half2*)&v.z);
                float2 f3 = __half22float2(*(__half2*)&v.w);
                a[0] = fmaf(f0.x, nm, a[0]);
                a[1] = fmaf(f0.y, nm, a[1]);
                a[2] = fmaf(f1.x, nm, a[2]);
                a[3] = fmaf(f1.y, nm, a[3]);
                a[4] = fmaf(f2.x, nm, a[4]);
                a[5] = fmaf(f2.y, nm, a[5]);
                a[6] = fmaf(f3.x, nm, a[6]);
                a[7] = fmaf(f3.y, nm, a[7]);
            }
        }

#pragma unroll
        for (int j = 0; j < 8; j++)
            a[j] += __shfl_xor_sync(0xffffffffu, a[j], 16);

        float dn  = g_dinv[node];
        float dn2 = dn * dn;
        uint4 sv = __ldg(((const uint4*)(g_h1 + (size_t)node * F_HID)) + l16);
        float2 s0 = __half22float2(*(__half2*)&sv.x);
        float2 s1 = __half22float2(*(__half2*)&sv.y);
        float2 s2 = __half22float2(*(__half2*)&sv.z);
        float2 s3 = __half22float2(*(__half2*)&sv.w);
        float h[8];
        h[0] = fmaxf(a[0] + s0.x * dn2 + bb[0], 0.f);
        h[1] = fmaxf(a[1] + s0.y * dn2 + bb[1], 0.f);
        h[2] = fmaxf(a[2] + s1.x * dn2 + bb[2], 0.f);
        h[3] = fmaxf(a[3] + s1.y * dn2 + bb[3], 0.f);
        h[4] = fmaxf(a[4] + s2.x * dn2 + bb[4], 0.f);
        h[5] = fmaxf(a[5] + s2.y * dn2 + bb[5], 0.f);
        h[6] = fmaxf(a[6] + s3.x * dn2 + bb[6], 0.f);
        h[7] = fmaxf(a[7] + s3.y * dn2 + bb[7], 0.f);

        if (half == 0) {
            __half2 o0 = __floats2half2_rn(h[0], h[1]);
            __half2 o1 = __floats2half2_rn(h[2], h[3]);
            __half2 o2 = __floats2half2_rn(h[4], h[5]);
            __half2 o3 = __floats2half2_rn(h[6], h[7]);
            ((uint4*)(g_h2 + (size_t)node * F_HID))[l16] =
                make_uint4(*(uint32_t*)&o0, *(uint32_t*)&o1,
                           *(uint32_t*)&o2, *(uint32_t*)&o3);
        }

        node = nnode;
        base = nbase;
        cnt  = ncnt;
    }
}

// ======================= kernel 5: GEMM2 via mma =============================
// g_z = h2 @ W2. CTA = 128 nodes; h2 tile in 4 SWZ64 panels (128r x 64B),
// W2^T (16r x 64B x 4 panels). Per warp: 16 rows, 2 n-subtiles, 8 k-steps.
#define G2_A 0
#define G2_B 32768
#define G2_SMEM (32768 + 4096)

__global__ __launch_bounds__(256, 2) void gemm2_k(int Nn) {
    extern __shared__ char smem[];
    uint32_t sb = smem_u32(smem);
    int tid  = threadIdx.x;
    int lane = tid & 31;
    int wid  = tid >> 5;
    int row0 = blockIdx.x * 128;

    // copy h2 tile: 4 panels x 128 rows x 4 x 16B = 2048 cp.async
#pragma unroll
    for (int i = 0; i < 8; i++) {
        int u = i * 256 + tid;
        int p = u >> 9;
        int rem = u & 511;
        int r = rem >> 2;
        int c = rem & 3;
        int gr = row0 + r;
        if (gr >= Nn) gr = Nn - 1;
        cp_async16(sb + G2_A + p * 8192 + SWZ64((uint32_t)(r * 64 + c * 16)),
                   g_h2 + (size_t)gr * F_HID + p * 32 + c * 8);
    }
    // copy W2^T: 4 panels x 16 rows x 4 x 16B = 256 cp.async
    if (tid < 256) {
        int p = tid >> 6;
        int rem = tid & 63;
        int r = rem >> 2;
        int c = rem & 3;
        cp_async16(sb + G2_B + p * 1024 + SWZ64((uint32_t)(r * 64 + c * 16)),
                   g_wt2 + (size_t)r * F_HID + p * 32 + c * 8);
    }
    CP_COMMIT();
    CP_WAIT0();
    __syncthreads();

    float acc[2][4];
#pragma unroll
    for (int nt = 0; nt < 2; nt++)
#pragma unroll
        for (int c = 0; c < 4; c++) acc[nt][c] = 0.f;

#pragma unroll
    for (int p = 0; p < 4; p++) {
#pragma unroll
        for (int ks = 0; ks < 2; ks++) {
            uint32_t a[4];
            uint32_t offA = SWZ64((uint32_t)((wid * 16 + (lane & 15)) * 64
                                             + ks * 32 + (lane >> 4) * 16));
            ldsm_x4(a, sb + G2_A + p * 8192 + offA);
            uint32_t b[4];
            uint32_t offB = SWZ64((uint32_t)(((lane & 7) + ((lane >> 4) & 1) * 8) * 64
                                             + ks * 32 + ((lane >> 3) & 1) * 16));
            ldsm_x4(b, sb + G2_B + p * 1024 + offB);
            mma_f16(acc[0], a, b + 0);
            mma_f16(acc[1], a, b + 2);
        }
    }

    int g4 = lane >> 2;
    int tg = lane & 3;
    int r0 = row0 + wid * 16 + g4;
#pragma unroll
    for (int nt = 0; nt < 2; nt++) {
        int c = nt * 8 + tg * 2;
        if (r0 < Nn)
            *(float2*)(g_z + (size_t)r0 * F_OUT + c) = make_float2(acc[nt][0], acc[nt][1]);
        if (r0 + 8 < Nn)
            *(float2*)(g_z + (size_t)(r0 + 8) * F_OUT + c) = make_float2(acc[nt][2], acc[nt][3]);
    }
}

// ======================= kernel 6: fused layer-2 =============================
// [byte-identical to round 16]
__global__ __launch_bounds__(256, 6) void agg2_fused_k(const float* __restrict__ b2,
                                                       float* __restrict__ out,
                                                       int Nn) {
    int lane16 = threadIdx.x & 15;
    int gid    = (blockIdx.x * blockDim.x + threadIdx.x) >> 4;
    int ngrp   = (gridDim.x * blockDim.x) >> 4;
    float bias = b2[lane16];

    int node = gid;
    int base = 0, cnt = 0;
    if (node < Nn) { base = g_off[node]; cnt = G_CNT[node]; }

    while (node < Nn) {
        int nnode = node + ngrp;
        int nbase = 0, ncnt = 0;
        if (nnode < Nn) { nbase = __ldg(g_off + nnode); ncnt = __ldg(G_CNT + nnode); }

        float acc[4] = {0.f, 0.f, 0.f, 0.f};
        for (int i = 0; i < cnt; i += 8) {
            const int4* ep = (const int4*)(g_edge + base + i);
            int4 p0 = __ldg(ep);
            int4 p1 = __ldg(ep + 1);
            int4 p2 = __ldg(ep + 2);
            int4 p3 = __ldg(ep + 3);
            float zv[8];
            zv[0] = __ldg(g_z + (size_t)p0.x * F_OUT + lane16);
            zv[1] = __ldg(g_z + (size_t)p0.z * F_OUT + lane16);
            zv[2] = __ldg(g_z + (size_t)p1.x * F_OUT + lane16);
            zv[3] = __ldg(g_z + (size_t)p1.z * F_OUT + lane16);
            zv[4] = __ldg(g_z + (size_t)p2.x * F_OUT + lane16);
            zv[5] = __ldg(g_z + (size_t)p2.z * F_OUT + lane16);
            zv[6] = __ldg(g_z + (size_t)p3.x * F_OUT + lane16);
            zv[7] = __ldg(g_z + (size_t)p3.z * F_OUT + lane16);
            acc[0] = fmaf(zv[0], __int_as_float(p0.y), acc[0]);
            acc[1] = fmaf(zv[1], __int_as_float(p0.w), acc[1]);
            acc[2] = fmaf(zv[2], __int_as_float(p1.y), acc[2]);
            acc[3] = fmaf(zv[3], __int_as_float(p1.w), acc[3]);
            acc[0] = fmaf(zv[4], __int_as_float(p2.y), acc[0]);
            acc[1] = fmaf(zv[5], __int_as_float(p2.w), acc[1]);
            acc[2] = fmaf(zv[6], __int_as_float(p3.y), acc[2]);
            acc[3] = fmaf(zv[7], __int_as_float(p3.w), acc[3]);
        }

        float dn  = g_dinv[node];
        float dn2 = dn * dn;
        float l = acc[0] + acc[1] + acc[2] + acc[3]
                + g_z[(size_t)node * F_OUT + lane16] * dn2 + bias;

        float m = l;
#pragma unroll
        for (int o = 8; o >= 1; o >>= 1)
            m = fmaxf(m, __shfl_xor_sync(0xffffffffu, m, o));
        float e = __expf(l - m);
        float sum = e;
#pragma unroll
        for (int o = 8; o >= 1; o >>= 1)
            sum += __shfl_xor_sync(0xffffffffu, sum, o);

        out[(size_t)node * F_OUT + lane16] = l - m - __logf(sum);

        node = nnode;
        base = nbase;
        cnt  = ncnt;
    }
}

// ---------------------------------------------------------------------------
extern "C" void kernel_launch(void* const* d_in, const int* in_sizes, int n_in,
                              void* d_out, int out_size) {
    const float* x  = (const float*)d_in[0];
    const int*   ei = (const int*)  d_in[1];
    const float* ew = (const float*)d_in[2];
    const float* W1 = (const float*)d_in[3];
    const float* b1 = (const float*)d_in[4];
    const float* W2 = (const float*)d_in[5];
    const float* b2 = (const float*)d_in[6];
    float* out = (float*)d_out;

    int Nn = in_sizes[0] / F_IN;
    int E  = in_sizes[1] / 2;
    const int* src = ei;
    const int* dst = ei + E;
    int nb = (Nn + SCAN_B - 1) / SCAN_B;

    static void* zptr = nullptr;
    static bool attr_set = false;
    if (!zptr) cudaGetSymbolAddress(&zptr, g_zblk);
    if (!attr_set) {
        cudaFuncSetAttribute(gemmscat_k, cudaFuncAttributeMaxDynamicSharedMemorySize,
                             GEMM_SMEM);
        cudaFuncSetAttribute(gemm2_k, cudaFuncAttributeMaxDynamicSharedMemorySize,
                             G2_SMEM);
        attr_set = true;
    }

    cudaMemsetAsync(zptr, 0, (size_t)(3 * MAXN + 4) * sizeof(int), 0);
    deg_cnt_k<<<(E + 255) / 256, 256>>>(dst, ew, E);                       // k1
    scanwconv_k<<<nb + 64, SCAN_B>>>(W1, W2, Nn, nb);                      // k2
    gemmscat_k<<<NSB + (Nn + 127) / 128, 256, GEMM_SMEM>>>(x, src, dst,
                                                           ew, Nn, E);    // k3
    agg1_gather_k<<<148 * 4, 256>>>(b1, Nn);                               // k4 <- profiled
    gemm2_k<<<(Nn + 127) / 128, 256, G2_SMEM>>>(Nn);                       // k5
    agg2_fused_k<<<148 * 6, 256>>>(b2, out, Nn);                           // k6
}